// round 10
// baseline (speedup 1.0000x reference)
#include <cuda_runtime.h>
#include <cstdint>

#define N_BATCH 4
#define PTILE 128
#define NTILES 32                 /* 4096/128 */
#define CELLS 528                 /* upper-triangle tile pairs */
#define TOTALB (CELLS*N_BATCH)
#define BLOCK 256
#define FSTR 136                  /* smem row stride (floats); 136%32=8 -> conflict-free frag loads */

__device__ double g_acc;
__device__ unsigned int g_done;

__device__ __forceinline__ float ex2f(float a) {
    float r; asm("ex2.approx.ftz.f32 %0, %1;" : "=f"(r) : "f"(a)); return r;
}
__device__ __forceinline__ float tf32r(float v) {
    uint32_t u; asm("cvt.rna.tf32.f32 %0, %1;" : "=r"(u) : "f"(v));
    return __uint_as_float(u);
}
__device__ __forceinline__ void mma8(float& d0, float& d1, float& d2, float& d3,
                                     uint32_t a0, uint32_t a1, uint32_t a2, uint32_t a3,
                                     uint32_t b0, uint32_t b1) {
    asm("mma.sync.aligned.m16n8k8.row.col.f32.tf32.tf32.f32 "
        "{%0,%1,%2,%3}, {%4,%5,%6,%7}, {%8,%9}, {%0,%1,%2,%3};"
        : "+f"(d0), "+f"(d1), "+f"(d2), "+f"(d3)
        : "r"(a0), "r"(a1), "r"(a2), "r"(a3), "r"(b0), "r"(b1));
}

// f[10] = {fx,fy,fr,fg,fb,h,s0,s1,s2,s3}; features pre-scaled by sqrt(log2 e),
// h = -0.5*||f_scaled||^2 so exp(-0.5 d^2) == ex2(h_p + h_q + f_p.f_q).
__device__ __forceinline__ void compute_pt(const float* __restrict__ img,
                                           const float* __restrict__ sg,
                                           int p, float* f) {
    const float SQL2E = 1.2011224087864498f;
    int y = p >> 6, x = p & 63;
    int ro = (y << 8) + (x << 1);
    float fx = (float)x * (SQL2E / 50.0f);
    float fy = (float)y * (SQL2E / 50.0f);
    float fr = img[ro]         * (SQL2E / 15.0f);
    float fg = img[16384 + ro] * (SQL2E / 15.0f);
    float fb = img[32768 + ro] * (SQL2E / 15.0f);
    float h  = -0.5f * (fx*fx + fy*fy + fr*fr + fg*fg + fb*fb);
    f[0]=fx; f[1]=fy; f[2]=fr; f[3]=fg; f[4]=fb; f[5]=h;
#pragma unroll
    for (int k = 0; k < 4; k++) {
        const float* sk = sg + k * 16384;
        f[6+k] = (sk[ro] + sk[ro+1] + sk[ro+128] + sk[ro+129]) * 0.25f;
    }
}

__global__ void __launch_bounds__(BLOCK) crf_kernel(const float* __restrict__ images,
                                                    const float* __restrict__ segs,
                                                    float* __restrict__ out) {
    __shared__ float sFA[24 * FSTR];   // p-tile, K-major (k slot, point)
    __shared__ float sFB[24 * FSTR];   // q-tile
    __shared__ float4 sSp[PTILE];
    __shared__ float4 sSq[PTILE];
    __shared__ float wsum[BLOCK / 32];

    int tid  = threadIdx.x;
    int w    = tid >> 5;
    int lane = tid & 31;
    int g    = lane & 3;    // frag column group
    int r    = lane >> 2;   // frag row
    int n = blockIdx.y;

    // decode upper-triangle cell t -> (I, J), J >= I
    int t = blockIdx.x;
    float ft = (float)t;
    int I = (int)((2.0f*NTILES + 1.0f - sqrtf((2.0f*NTILES+1.0f)*(2.0f*NTILES+1.0f) - 8.0f*ft)) * 0.5f);
    while (I * NTILES - (I * (I - 1)) / 2 > t) I--;
    while ((I + 1) * NTILES - ((I + 1) * I) / 2 <= t) I++;
    int J = I + (t - (I * NTILES - (I * (I - 1)) / 2));

    const float* img = images + (size_t)n * 3 * 16384;
    const float* sg  = segs   + (size_t)n * 4 * 16384;

    // ---- fill feature tiles: tid<128 -> p side (A layout), tid>=128 -> q side (B layout) ----
    {
        int side = tid >> 7;          // 0 = A(p), 1 = B(q)
        int idx  = tid & 127;
        float f[10];
        compute_pt(img, sg, (side ? J : I) * PTILE + idx, f);
        float* F = side ? sFB : sFA;

        float hi[5], lo[5];
#pragma unroll
        for (int d = 0; d < 5; d++) {
            hi[d] = tf32r(f[d]);
            lo[d] = tf32r(f[d] - hi[d]);
        }
        float hh = tf32r(f[5]);
        float hl = tf32r(f[5] - hh);

        if (side == 0) {
            // A slots: 0-4 hi, 5-9 hi, 10-14 lo, 15 h_hi, 16 h_lo, 17 1, 18 1, 19-23 0
#pragma unroll
            for (int d = 0; d < 5; d++) {
                F[d * FSTR + idx]        = hi[d];
                F[(5 + d) * FSTR + idx]  = hi[d];
                F[(10 + d) * FSTR + idx] = lo[d];
            }
            F[15 * FSTR + idx] = hh;
            F[16 * FSTR + idx] = hl;
            F[17 * FSTR + idx] = 1.0f;
            F[18 * FSTR + idx] = 1.0f;
            sSp[idx] = make_float4(f[6], f[7], f[8], f[9]);
        } else {
            // B slots: 0-4 hi, 5-9 lo, 10-14 hi, 15 1, 16 1, 17 h_hi, 18 h_lo, 19-23 0
#pragma unroll
            for (int d = 0; d < 5; d++) {
                F[d * FSTR + idx]        = hi[d];
                F[(5 + d) * FSTR + idx]  = lo[d];
                F[(10 + d) * FSTR + idx] = hi[d];
            }
            F[15 * FSTR + idx] = 1.0f;
            F[16 * FSTR + idx] = 1.0f;
            F[17 * FSTR + idx] = hh;
            F[18 * FSTR + idx] = hl;
            sSq[idx] = make_float4(f[6], f[7], f[8], f[9]);
        }
#pragma unroll
        for (int k = 19; k < 24; k++)
            F[k * FSTR + idx] = 0.0f;
    }
    __syncthreads();

    // ---- per-warp: p-rows [16w, 16w+16), all q via 16 n-chunks of 8 ----
    int base = 16 * w;

    // A fragments, loaded once (K=24 -> 3 k-steps)
    uint32_t A[3][4];
#pragma unroll
    for (int ks = 0; ks < 3; ks++) {
        int k0 = 8 * ks;
        A[ks][0] = __float_as_uint(sFA[(k0 + g) * FSTR + base + r]);
        A[ks][1] = __float_as_uint(sFA[(k0 + g) * FSTR + base + r + 8]);
        A[ks][2] = __float_as_uint(sFA[(k0 + g + 4) * FSTR + base + r]);
        A[ks][3] = __float_as_uint(sFA[(k0 + g + 4) * FSTR + base + r + 8]);
    }

    float aA0=0.f, aA1=0.f, aA2=0.f, aA3=0.f;   // row base+r   per-class accum
    float aB0=0.f, aB1=0.f, aB2=0.f, aB3=0.f;   // row base+r+8

#pragma unroll 2
    for (int j = 0; j < 16; j++) {
        int n0 = 8 * j;
        float d0 = 0.f, d1 = 0.f, d2 = 0.f, d3 = 0.f;
#pragma unroll
        for (int ks = 0; ks < 3; ks++) {
            int k0 = 8 * ks;
            uint32_t b0 = __float_as_uint(sFB[(k0 + g) * FSTR + n0 + r]);
            uint32_t b1 = __float_as_uint(sFB[(k0 + g + 4) * FSTR + n0 + r]);
            mma8(d0, d1, d2, d3, A[ks][0], A[ks][1], A[ks][2], A[ks][3], b0, b1);
        }
        // c-frag: d0=(r, 2g) d1=(r, 2g+1) d2=(r+8, 2g) d3=(r+8, 2g+1); cols = q within chunk
        float e0 = ex2f(d0);
        float e1 = ex2f(d1);
        float e2 = ex2f(d2);
        float e3 = ex2f(d3);
        int q0 = n0 + 2 * g;
        float4 s0 = sSq[q0];
        float4 s1 = sSq[q0 + 1];
        aA0 = fmaf(e0, s0.x, aA0); aA0 = fmaf(e1, s1.x, aA0);
        aA1 = fmaf(e0, s0.y, aA1); aA1 = fmaf(e1, s1.y, aA1);
        aA2 = fmaf(e0, s0.z, aA2); aA2 = fmaf(e1, s1.z, aA2);
        aA3 = fmaf(e0, s0.w, aA3); aA3 = fmaf(e1, s1.w, aA3);
        aB0 = fmaf(e2, s0.x, aB0); aB0 = fmaf(e3, s1.x, aB0);
        aB1 = fmaf(e2, s0.y, aB1); aB1 = fmaf(e3, s1.y, aB1);
        aB2 = fmaf(e2, s0.z, aB2); aB2 = fmaf(e3, s1.z, aB2);
        aB3 = fmaf(e2, s0.w, aB3); aB3 = fmaf(e3, s1.w, aB3);
    }

    // sum the 4 lanes (g=0..3) sharing each row: butterfly over lane bits 0-1
#pragma unroll
    for (int mask = 1; mask <= 2; mask <<= 1) {
        aA0 += __shfl_xor_sync(0xFFFFFFFFu, aA0, mask);
        aA1 += __shfl_xor_sync(0xFFFFFFFFu, aA1, mask);
        aA2 += __shfl_xor_sync(0xFFFFFFFFu, aA2, mask);
        aA3 += __shfl_xor_sync(0xFFFFFFFFu, aA3, mask);
        aB0 += __shfl_xor_sync(0xFFFFFFFFu, aB0, mask);
        aB1 += __shfl_xor_sync(0xFFFFFFFFu, aB1, mask);
        aB2 += __shfl_xor_sync(0xFFFFFFFFu, aB2, mask);
        aB3 += __shfl_xor_sync(0xFFFFFFFFu, aB3, mask);
    }

    float acc = 0.0f;
    if (g == 0) {
        float4 p0 = sSp[base + r];
        float4 p8 = sSp[base + r + 8];
        float ra = p0.x * aA0;
        ra = fmaf(p0.y, aA1, ra);
        ra = fmaf(p0.z, aA2, ra);
        ra = fmaf(p0.w, aA3, ra);
        float rb = p8.x * aB0;
        rb = fmaf(p8.y, aB1, rb);
        rb = fmaf(p8.z, aB2, rb);
        rb = fmaf(p8.w, aB3, rb);
        acc = ra + rb;
        if (I != J) acc *= 2.0f;   // symmetric off-diagonal cell
    }

    // warp + block reduce, one double atomic per block
#pragma unroll
    for (int off = 16; off > 0; off >>= 1)
        acc += __shfl_down_sync(0xFFFFFFFFu, acc, off);
    if (lane == 0) wsum[w] = acc;
    __syncthreads();
    if (tid == 0) {
        float s = 0.0f;
#pragma unroll
        for (int i = 0; i < BLOCK / 32; i++) s += wsum[i];
        atomicAdd(&g_acc, (double)s);
        __threadfence();
        unsigned int d = atomicAdd(&g_done, 1u);
        if (d == TOTALB - 1u) {
            double total = *((volatile double*)&g_acc);
            out[0] = (float)(total * (-1e-7 / (double)N_BATCH));
            g_acc = 0.0;          // reset for next graph replay
            g_done = 0u;
        }
    }
}

extern "C" void kernel_launch(void* const* d_in, const int* in_sizes, int n_in,
                              void* d_out, int out_size) {
    const float* images = (const float*)d_in[0];
    const float* segs   = (const float*)d_in[1];
    dim3 grid(CELLS, N_BATCH);
    crf_kernel<<<grid, BLOCK>>>(images, segs, (float*)d_out);
}

// round 11
// speedup vs baseline: 1.1828x; 1.1828x over previous
#include <cuda_runtime.h>
#include <cstdint>

#define N_BATCH 4
#define PTILE 128
#define NTILES 32                 /* 4096/128 */
#define CELLS 528                 /* upper-triangle tile pairs */
#define TOTALB (CELLS*N_BATCH)
#define BLOCK 256
#define FSTR 136                  /* smem row stride (floats); %32==8 -> conflict-free */
#define SLOTS 28                  /* 24 D-slots + 4 G-slots */

__device__ double g_acc;
__device__ unsigned int g_done;

__device__ __forceinline__ float ex2f(float a) {
    float r; asm("ex2.approx.ftz.f32 %0, %1;" : "=f"(r) : "f"(a)); return r;
}
__device__ __forceinline__ float tf32r(float v) {
    uint32_t u; asm("cvt.rna.tf32.f32 %0, %1;" : "=r"(u) : "f"(v));
    return __uint_as_float(u);
}
__device__ __forceinline__ void mma8(float& d0, float& d1, float& d2, float& d3,
                                     uint32_t a0, uint32_t a1, uint32_t a2, uint32_t a3,
                                     uint32_t b0, uint32_t b1) {
    asm("mma.sync.aligned.m16n8k8.row.col.f32.tf32.tf32.f32 "
        "{%0,%1,%2,%3}, {%4,%5,%6,%7}, {%8,%9}, {%0,%1,%2,%3};"
        : "+f"(d0), "+f"(d1), "+f"(d2), "+f"(d3)
        : "r"(a0), "r"(a1), "r"(a2), "r"(a3), "r"(b0), "r"(b1));
}

// f[10] = {fx,fy,fr,fg,fb,h,s0,s1,s2,s3}; features pre-scaled by sqrt(log2 e),
// h = -0.5*||f_scaled||^2 so exp(-0.5 d^2) == ex2(h_p + h_q + f_p.f_q).
__device__ __forceinline__ void compute_pt(const float* __restrict__ img,
                                           const float* __restrict__ sg,
                                           int p, float* f) {
    const float SQL2E = 1.2011224087864498f;
    int y = p >> 6, x = p & 63;
    int ro = (y << 8) + (x << 1);
    float fx = (float)x * (SQL2E / 50.0f);
    float fy = (float)y * (SQL2E / 50.0f);
    float fr = img[ro]         * (SQL2E / 15.0f);
    float fg = img[16384 + ro] * (SQL2E / 15.0f);
    float fb = img[32768 + ro] * (SQL2E / 15.0f);
    float h  = -0.5f * (fx*fx + fy*fy + fr*fr + fg*fg + fb*fb);
    f[0]=fx; f[1]=fy; f[2]=fr; f[3]=fg; f[4]=fb; f[5]=h;
#pragma unroll
    for (int k = 0; k < 4; k++) {
        const float* sk = sg + k * 16384;
        f[6+k] = (sk[ro] + sk[ro+1] + sk[ro+128] + sk[ro+129]) * 0.25f;
    }
}

__global__ void __launch_bounds__(BLOCK) crf_kernel(const float* __restrict__ images,
                                                    const float* __restrict__ segs,
                                                    float* __restrict__ out) {
    __shared__ float sFA[SLOTS * FSTR];   // p-tile, slot-major
    __shared__ float sFB[SLOTS * FSTR];   // q-tile
    __shared__ float wsum[BLOCK / 32];

    int tid  = threadIdx.x;
    int w    = tid >> 5;
    int lane = tid & 31;
    int g    = lane & 3;    // frag column group
    int r    = lane >> 2;   // frag row
    int n = blockIdx.y;

    // decode upper-triangle cell t -> (I, J), J >= I
    int t = blockIdx.x;
    float ft = (float)t;
    int I = (int)((2.0f*NTILES + 1.0f - sqrtf((2.0f*NTILES+1.0f)*(2.0f*NTILES+1.0f) - 8.0f*ft)) * 0.5f);
    while (I * NTILES - (I * (I - 1)) / 2 > t) I--;
    while ((I + 1) * NTILES - ((I + 1) * I) / 2 <= t) I++;
    int J = I + (t - (I * NTILES - (I * (I - 1)) / 2));

    const float* img = images + (size_t)n * 3 * 16384;
    const float* sg  = segs   + (size_t)n * 4 * 16384;

    // ---- fill feature tiles: tid<128 -> p side (A layout), tid>=128 -> q side (B layout) ----
    {
        int side = tid >> 7;          // 0 = A(p), 1 = B(q)
        int idx  = tid & 127;
        float f[10];
        compute_pt(img, sg, (side ? J : I) * PTILE + idx, f);
        float* F = side ? sFB : sFA;

        float hi[5], lo[5];
#pragma unroll
        for (int d = 0; d < 5; d++) {
            hi[d] = tf32r(f[d]);
            lo[d] = tf32r(f[d] - hi[d]);
        }
        float hh = tf32r(f[5]);
        float hl = tf32r(f[5] - hh);

        if (side == 0) {
            // A D-slots: 0-4 hi, 5-9 hi, 10-14 lo, 15 h_hi, 16 h_lo, 17 1, 18 1, 19-23 0
#pragma unroll
            for (int d = 0; d < 5; d++) {
                F[d * FSTR + idx]        = hi[d];
                F[(5 + d) * FSTR + idx]  = hi[d];
                F[(10 + d) * FSTR + idx] = lo[d];
            }
            F[15 * FSTR + idx] = hh;
            F[16 * FSTR + idx] = hl;
            F[17 * FSTR + idx] = 1.0f;
            F[18 * FSTR + idx] = 1.0f;
        } else {
            // B D-slots: 0-4 hi, 5-9 lo, 10-14 hi, 15 1, 16 1, 17 h_hi, 18 h_lo, 19-23 0
#pragma unroll
            for (int d = 0; d < 5; d++) {
                F[d * FSTR + idx]        = hi[d];
                F[(5 + d) * FSTR + idx]  = lo[d];
                F[(10 + d) * FSTR + idx] = hi[d];
            }
            F[15 * FSTR + idx] = 1.0f;
            F[16 * FSTR + idx] = 1.0f;
            F[17 * FSTR + idx] = hh;
            F[18 * FSTR + idx] = hl;
        }
#pragma unroll
        for (int k = 19; k < 24; k++)
            F[k * FSTR + idx] = 0.0f;
        // G-slots 24-27: seg vector in tf32 (same on both sides)
#pragma unroll
        for (int k = 0; k < 4; k++)
            F[(24 + k) * FSTR + idx] = tf32r(f[6 + k]);
    }
    __syncthreads();

    // ---- per-warp: p-rows [16w, 16w+16), all q via 16 n-chunks of 8 ----
    int base = 16 * w;

    // D A-fragments (K=24 -> 3 k-steps), loaded once
    uint32_t A[3][4];
#pragma unroll
    for (int ks = 0; ks < 3; ks++) {
        int k0 = 8 * ks;
        A[ks][0] = __float_as_uint(sFA[(k0 + g) * FSTR + base + r]);
        A[ks][1] = __float_as_uint(sFA[(k0 + g) * FSTR + base + r + 8]);
        A[ks][2] = __float_as_uint(sFA[(k0 + g + 4) * FSTR + base + r]);
        A[ks][3] = __float_as_uint(sFA[(k0 + g + 4) * FSTR + base + r + 8]);
    }
    // G A-fragments (K=8 step, slots 24-27 live, 28-31 implicit zero)
    uint32_t GA0 = __float_as_uint(sFA[(24 + g) * FSTR + base + r]);
    uint32_t GA1 = __float_as_uint(sFA[(24 + g) * FSTR + base + r + 8]);

    float acc = 0.0f;

#pragma unroll 2
    for (int j = 0; j < 16; j++) {
        int n0 = 8 * j;

        // D = arg matrix
        float d0 = 0.f, d1 = 0.f, d2 = 0.f, d3 = 0.f;
#pragma unroll
        for (int ks = 0; ks < 3; ks++) {
            int k0 = 8 * ks;
            uint32_t b0 = __float_as_uint(sFB[(k0 + g) * FSTR + n0 + r]);
            uint32_t b1 = __float_as_uint(sFB[(k0 + g + 4) * FSTR + n0 + r]);
            mma8(d0, d1, d2, d3, A[ks][0], A[ks][1], A[ks][2], A[ks][3], b0, b1);
        }

        // G = seg Gram matrix (same c-frag positions as D)
        float g0 = 0.f, g1 = 0.f, g2 = 0.f, g3 = 0.f;
        {
            uint32_t gb0 = __float_as_uint(sFB[(24 + g) * FSTR + n0 + r]);
            mma8(g0, g1, g2, g3, GA0, GA1, 0u, 0u, gb0, 0u);
        }

        acc = fmaf(ex2f(d0), g0, acc);
        acc = fmaf(ex2f(d1), g1, acc);
        acc = fmaf(ex2f(d2), g2, acc);
        acc = fmaf(ex2f(d3), g3, acc);
    }

    if (I != J) acc *= 2.0f;   // symmetric off-diagonal cell

    // warp + block reduce, one double atomic per block
#pragma unroll
    for (int off = 16; off > 0; off >>= 1)
        acc += __shfl_down_sync(0xFFFFFFFFu, acc, off);
    if (lane == 0) wsum[w] = acc;
    __syncthreads();
    if (tid == 0) {
        float s = 0.0f;
#pragma unroll
        for (int i = 0; i < BLOCK / 32; i++) s += wsum[i];
        atomicAdd(&g_acc, (double)s);
        __threadfence();
        unsigned int d = atomicAdd(&g_done, 1u);
        if (d == TOTALB - 1u) {
            double total = *((volatile double*)&g_acc);
            out[0] = (float)(total * (-1e-7 / (double)N_BATCH));
            g_acc = 0.0;          // reset for next graph replay
            g_done = 0u;
        }
    }
}

extern "C" void kernel_launch(void* const* d_in, const int* in_sizes, int n_in,
                              void* d_out, int out_size) {
    const float* images = (const float*)d_in[0];
    const float* segs   = (const float*)d_in[1];
    dim3 grid(CELLS, N_BATCH);
    crf_kernel<<<grid, BLOCK>>>(images, segs, (float*)d_out);
}